// round 16
// baseline (speedup 1.0000x reference)
#include <cuda_runtime.h>

#define WI 512
#define HI 512
#define BN 8
#define CN 8
#define HW (HI * WI)
#define TPB 256
#define NBLK ((BN * HW) / TPB)   // 8192

// Accumulators (module-load zeroed; last block resets them each call so the
// kernel stays deterministic across graph replays).
__device__ double g_big;        // sum over B*C*H*W weighted terms
__device__ double g_small;      // sum over B*1*H*W terms (bce1 + de2)
__device__ unsigned g_ticket;   // completion ticket

// sigmoid via single MUFU.TANH: sigma(x) = 0.5*tanh(x/2) + 0.5
__device__ __forceinline__ float sigf(float x) {
    float t;
    asm("tanh.approx.f32 %0, %1;" : "=f"(t) : "f"(0.5f * x));
    return fmaf(0.5f, t, 0.5f);
}
#define CLOG2_MIN (-144.26950408889634f)   // -100 / ln2
__device__ __forceinline__ float clog2f_(float x) {
    return fmaxf(__log2f(x), CLOG2_MIN);
}

__global__ void __launch_bounds__(TPB, 6) loss_k(
    const float* __restrict__ atts, const float* __restrict__ dets,
    const float* __restrict__ target, const float* __restrict__ con,
    float* __restrict__ out)
{
    int idx = blockIdx.x * TPB + threadIdx.x;   // [0, B*H*W)
    int w = idx & (WI - 1);
    int r = (idx >> 9) & (HI - 1);
    int b = idx >> 18;
    int off = r * WI + w;

    const float* A = atts + (size_t)b * CN * HW;
    const float* D = dets + (size_t)b * CN * HW;
    const float* C = con  + (size_t)b * CN * HW;

    // neighbor offsets for plane j = 7-ch (indexed by j)
    const int drt[8] = { 1, 1, 1, 0, 0, -1, -1, -1 };
    const int dwt[8] = { 1, 0, -1, 1, -1, 1, 0, -1 };

    // Streaming per-channel accumulation: small live set -> low reg count.
    float prodP = 1.0f, prodV = 1.0f, extra = 0.0f;
    float g1 = 0.0f, g2 = 0.0f, s = 0.0f, vmin = 2.0f;

#pragma unroll
    for (int ch = 0; ch < 8; ch++) {
        const int j = 7 - ch;
        const int dr = drt[j], dw = dwt[j];     // compile-time per iteration
        const int noff = off + dr * WI + dw;    // immediate offset from off

        float pa = sigf(__ldg(A + ch * HW + off));
        float pd = sigf(__ldg(D + ch * HW + off));

        // shifts zero-pad the PROBABILITY -> OOB neighbor prob = exactly 0.0
        bool val = ((unsigned)(r + dr) < (unsigned)HI) &&
                   ((unsigned)(w + dw) < (unsigned)WI);
        float n1 = val ? sigf(__ldg(A + j * HW + noff)) : 0.0f;
        float n2 = val ? sigf(__ldg(D + j * HW + noff)) : 0.0f;

        float v1 = pa * n1;   // vote ch = p[ch] * prob[7-ch] shifted
        float v2 = pd * n2;

        float t = __ldg(C + ch * HW + off);     // binary 0/1
        s += t;
        bool tt = t > 0.5f;
        float fa = tt ? pa : 1.0f - pa;
        float fd = tt ? pd : 1.0f - pd;
        prodP *= fa * fd;
        float f1 = tt ? v1 : 1.0f - v1;
        float f2 = tt ? v2 : 1.0f - v2;
        // f1 == 0 only at zero-padded borders with t==1, and then f2 == 0 too
        // (identical padding geometry): both clamp to -100, weight 0.2 -> -40.
        if (f1 == 0.0f) extra += -40.0f;
        else            prodV *= f1 * f2;
        g1 += v1; g2 += v2;
        vmin = fminf(vmin, v2);
    }

    const float LN2 = 0.69314718055994531f;
    float big = LN2 * (0.8f * __log2f(prodP) + 0.2f * __log2f(prodV)) + extra;

    g1 *= 0.125f;   // glo_map1
    g2 *= 0.125f;   // glo_map2

    float tg = __ldg(target + (size_t)b * HW + off);
    bool tt = tg > 0.5f;
    float sm2 = clog2f_(tt ? g1 : 1.0f - g1);    // bce_loss1 (log2 domain)
    bool edge = (s > 0.5f) && (s < 7.5f);        // 0 < sum(con) < 8
    float dec = edge ? (1.0f - vmin) : g2;       // decouple_map
    sm2 += clog2f_(tt ? dec : 1.0f - dec);       // de_loss2
    float small = LN2 * sm2;

    // ---- block reduction (two floats) ----
#pragma unroll
    for (int o = 16; o > 0; o >>= 1) {
        big   += __shfl_down_sync(0xffffffffu, big, o);
        small += __shfl_down_sync(0xffffffffu, small, o);
    }
    __shared__ float sb[8], ss[8];
    int lane = threadIdx.x & 31;
    int wid  = threadIdx.x >> 5;
    if (lane == 0) { sb[wid] = big; ss[wid] = small; }
    __syncthreads();
    if (wid == 0) {
        big   = (lane < 8) ? sb[lane] : 0.0f;
        small = (lane < 8) ? ss[lane] : 0.0f;
#pragma unroll
        for (int o = 4; o > 0; o >>= 1) {
            big   += __shfl_down_sync(0xffffffffu, big, o);
            small += __shfl_down_sync(0xffffffffu, small, o);
        }
        if (lane == 0) {
            atomicAdd(&g_big,   (double)big);
            atomicAdd(&g_small, (double)small);
            __threadfence();
            unsigned t = atomicAdd(&g_ticket, 1u);
            if (t == (unsigned)(NBLK - 1)) {
                // last block: finalize, write output, reset for next replay
                double B = atomicAdd(&g_big,   0.0);   // L2-coherent read
                double S = atomicAdd(&g_small, 0.0);
                const double N8 = (double)BN * CN * HW;  // 16777216
                const double N1 = (double)BN * HW;       // 2097152
                out[0] = (float)(-(B / N8) - (S / N1));
                g_big = 0.0;
                g_small = 0.0;
                __threadfence();
                g_ticket = 0u;
            }
        }
    }
}

extern "C" void kernel_launch(void* const* d_in, const int* in_sizes, int n_in,
                              void* d_out, int out_size) {
    const float* atts   = (const float*)d_in[0];
    const float* dets   = (const float*)d_in[1];
    const float* target = (const float*)d_in[2];
    const float* con    = (const float*)d_in[3];
    float* out = (float*)d_out;

    loss_k<<<NBLK, TPB>>>(atts, dets, target, con, out);
}